// round 16
// baseline (speedup 1.0000x reference)
#include <cuda_runtime.h>

// FlowComposite: flows [B,T,2,H,W] fp32 -> out [B,2,H,W] fp32.
// FINAL — converged best (R10 config; best harness 182.4us, ncu 181.6us,
// rel_err 0.0; five identical re-measurements within ±0.7us).
//
// One thread per output pixel runs the 12-step composition chain in
// registers (chains are pixel-independent). Per step: 8 independent scalar
// LDG.32 gathers (4 bilinear corners x 2 channels).
//
// Design facts, all HW-measured this session (sm_103a, iid-normal flows):
// - Binding pipe: L1tex gather wavefronts (95% busy; ~3.7 lines/request,
//   data-dependent). DRAM = exactly compulsory 434 MB @ 2.38 TB/s;
//   L2/ALU/issue all slack.
// - Scalar LDG.32 is the cheapest divergent gather mode: float2 merge +23%,
//   float4 merge +80% (per-request return-bandwidth floors).
// - Warp footprint 32x1 contiguous-x optimal: 16x2 +11% (extra base rows
//   cost more wavefronts than narrower x-span saves).
// - Cross-chain corner sharing loses: shuffle +3%, thread-pair +40%
//   (neighboring chains decorrelate; ~30-40% hit rate).
// - Reduced-precision staging excluded: chain amplifies perturbations ~1e3x
//   (1e-7-scale rounding change -> 4.3e-4 rel_err measured).
// - Exactness: px=(x+u)-0.5 rounding order (no hoist), sum
//   ((c00+c10)+c01)+c11, single-rounded wx*wy with exact 1.0/0.0 validity
//   fold. t=0 exact-uniform (weights = 0.25*validity, coherent loads).
// - 32x8 block tile: warps 128B-line-aligned in x, 8 rows per L1 for
//   vertical gather-line reuse (L2 63.8% -> 31.6%).

static constexpr int Bc = 8;
static constexpr int Tc = 12;
static constexpr int Hc = 544;
static constexpr int Wc = 960;
static constexpr int HW = Hc * Wc;

__global__ __launch_bounds__(256)
void flow_composite_kernel(const float* __restrict__ flows, float* __restrict__ out) {
    // 32x8 pixel tile per block; warp = 32 contiguous x (128B-aligned base).
    const int x = (blockIdx.x << 5) + (threadIdx.x & 31);
    const int y = (blockIdx.y << 3) + (threadIdx.x >> 5);
    const int b = blockIdx.z;

    const float xf = (float)x;
    const float yf = (float)y;

    const float* fb = flows + (unsigned)b * (Tc * 2 * HW);

    // ---- t = 0: u=v=0 exactly -> px = x-0.5 -> weights exactly 0.25*valid,
    // corners (x-1,x)x(y-1,y): fully coherent loads.
    float u, v;
    {
        const float* f0 = fb;
        const float* f1 = fb + HW;

        const int xm = max(x - 1, 0);
        const int ym = max(y - 1, 0);
        const int r0 = ym * Wc;
        const int r1 = y * Wc;

        const float vx = (x >= 1) ? 1.0f : 0.0f;
        const float vy = (y >= 1) ? 1.0f : 0.0f;
        const float w00 = 0.25f * (vx * vy);
        const float w10 = 0.25f * vy;
        const float w01 = 0.25f * vx;
        const float w11 = 0.25f;

        const float a00 = __ldg(f0 + r0 + xm);
        const float a10 = __ldg(f0 + r0 + x);
        const float a01 = __ldg(f0 + r1 + xm);
        const float a11 = __ldg(f0 + r1 + x);
        const float b00 = __ldg(f1 + r0 + xm);
        const float b10 = __ldg(f1 + r0 + x);
        const float b01 = __ldg(f1 + r1 + xm);
        const float b11 = __ldg(f1 + r1 + x);

        u = ((w00 * a00 + w10 * a10) + w01 * a01) + w11 * a11;
        v = ((w00 * b00 + w10 * b10) + w01 * b01) + w11 * b11;
    }

    // ---- t = 1..11: divergent scalar gathers, reference rounding order.
    #pragma unroll
    for (int t = 1; t < Tc; ++t) {
        const float* f0 = fb + (unsigned)t * (2 * HW);   // u plane
        const float* f1 = f0 + HW;                       // v plane

        // Reference order: (x + u) - 0.5 (do NOT hoist the -0.5).
        const float px = (xf + u) - 0.5f;
        const float py = (yf + v) - 0.5f;

        const int x0 = __float2int_rd(px);
        const int y0 = __float2int_rd(py);

        const float wx1 = px - (float)x0;
        const float wy1 = py - (float)y0;
        const float wx0 = 1.0f - wx1;
        const float wy0 = 1.0f - wy1;

        // Fold validity into axis weights (exact: x1.0 / x0.0).
        const float gx0 = ((x0 >= 0)  && (x0 <= Wc - 1)) ? wx0 : 0.0f;
        const float gx1 = ((x0 >= -1) && (x0 <= Wc - 2)) ? wx1 : 0.0f;
        const float gy0 = ((y0 >= 0)  && (y0 <= Hc - 1)) ? wy0 : 0.0f;
        const float gy1 = ((y0 >= -1) && (y0 <= Hc - 2)) ? wy1 : 0.0f;

        const float w00 = gx0 * gy0;
        const float w10 = gx1 * gy0;
        const float w01 = gx0 * gy1;
        const float w11 = gx1 * gy1;

        const int xc0 = min(max(x0, 0), Wc - 1);
        const int xc1 = min(max(x0 + 1, 0), Wc - 1);
        const int yc0 = min(max(y0, 0), Hc - 1);
        const int yc1 = min(max(y0 + 1, 0), Hc - 1);

        const int r0 = yc0 * Wc;
        const int r1 = yc1 * Wc;
        const int i00 = r0 + xc0;
        const int i10 = r0 + xc1;
        const int i01 = r1 + xc0;
        const int i11 = r1 + xc1;

        // 8 independent scalar gathers -> MLP 8.
        const float a00 = __ldg(f0 + i00);
        const float a10 = __ldg(f0 + i10);
        const float a01 = __ldg(f0 + i01);
        const float a11 = __ldg(f0 + i11);
        const float b00 = __ldg(f1 + i00);
        const float b10 = __ldg(f1 + i10);
        const float b01 = __ldg(f1 + i01);
        const float b11 = __ldg(f1 + i11);

        // Same summation order as reference: ((c00 + c10) + c01) + c11
        const float s0 = ((w00 * a00 + w10 * a10) + w01 * a01) + w11 * a11;
        const float s1 = ((w00 * b00 + w10 * b10) + w01 * b01) + w11 * b11;

        u += s0;
        v += s1;
    }

    const int p = y * Wc + x;
    float* ob = out + (unsigned)b * (2 * HW);
    ob[p]      = u;
    ob[HW + p] = v;
}

extern "C" void kernel_launch(void* const* d_in, const int* in_sizes, int n_in,
                              void* d_out, int out_size) {
    const float* flows = (const float*)d_in[0];
    float* out = (float*)d_out;

    dim3 grid(Wc / 32, Hc / 8, Bc);   // 30 x 68 x 8, exact cover
    dim3 block(256);
    flow_composite_kernel<<<grid, block>>>(flows, out);
}

// round 17
// speedup vs baseline: 1.0088x; 1.0088x over previous
#include <cuda_runtime.h>

// FlowComposite: flows [B,T,2,H,W] fp32 -> out [B,2,H,W] fp32.
// FINAL — converged (best harness 182.4us, ncu 181.6-182.5us, rel_err 0.0;
// six identical re-measurements within the noise band).
//
// One thread per output pixel runs the 12-step composition chain in
// registers (chains are pixel-independent). Per step: 8 independent scalar
// LDG.32 gathers (4 bilinear corners x 2 channels).
//
// Design facts, all HW-measured this session (sm_103a, iid-normal flows):
// - Binding pipe: L1tex gather wavefronts (95% busy; ~3.7 lines/request,
//   data-dependent). DRAM = exactly compulsory 434 MB @ 2.38 TB/s;
//   L2/ALU/issue all slack.
// - Scalar LDG.32 is the cheapest divergent gather mode: float2 merge +23%,
//   float4 merge +80% (per-request return-bandwidth floors).
// - Warp footprint 32x1 contiguous-x optimal: 16x2 +11% (extra base rows
//   cost more wavefronts than narrower x-span saves).
// - Cross-chain corner sharing loses: shuffle +3%, thread-pair +40%
//   (neighboring chains decorrelate; ~30-40% hit rate).
// - Reduced-precision / texture staging excluded: chain amplifies
//   perturbations ~1e3x (measured); TMU coordinate snapping can disagree
//   with floorf -> wrong-corner O(1) errors.
// - uv-interleave pre-pass loses: 802 MB restream >= main-kernel saving.
// - Exactness: px=(x+u)-0.5 rounding order (no hoist), sum
//   ((c00+c10)+c01)+c11, single-rounded wx*wy with exact 1.0/0.0 validity
//   fold. t=0 exact-uniform (weights = 0.25*validity, coherent loads).
// - 32x8 block tile: warps 128B-line-aligned in x, 8 rows per L1 for
//   vertical gather-line reuse (L2 63.8% -> 31.6%).

static constexpr int Bc = 8;
static constexpr int Tc = 12;
static constexpr int Hc = 544;
static constexpr int Wc = 960;
static constexpr int HW = Hc * Wc;

__global__ __launch_bounds__(256)
void flow_composite_kernel(const float* __restrict__ flows, float* __restrict__ out) {
    // 32x8 pixel tile per block; warp = 32 contiguous x (128B-aligned base).
    const int x = (blockIdx.x << 5) + (threadIdx.x & 31);
    const int y = (blockIdx.y << 3) + (threadIdx.x >> 5);
    const int b = blockIdx.z;

    const float xf = (float)x;
    const float yf = (float)y;

    const float* fb = flows + (unsigned)b * (Tc * 2 * HW);

    // ---- t = 0: u=v=0 exactly -> px = x-0.5 -> weights exactly 0.25*valid,
    // corners (x-1,x)x(y-1,y): fully coherent loads.
    float u, v;
    {
        const float* f0 = fb;
        const float* f1 = fb + HW;

        const int xm = max(x - 1, 0);
        const int ym = max(y - 1, 0);
        const int r0 = ym * Wc;
        const int r1 = y * Wc;

        const float vx = (x >= 1) ? 1.0f : 0.0f;
        const float vy = (y >= 1) ? 1.0f : 0.0f;
        const float w00 = 0.25f * (vx * vy);
        const float w10 = 0.25f * vy;
        const float w01 = 0.25f * vx;
        const float w11 = 0.25f;

        const float a00 = __ldg(f0 + r0 + xm);
        const float a10 = __ldg(f0 + r0 + x);
        const float a01 = __ldg(f0 + r1 + xm);
        const float a11 = __ldg(f0 + r1 + x);
        const float b00 = __ldg(f1 + r0 + xm);
        const float b10 = __ldg(f1 + r0 + x);
        const float b01 = __ldg(f1 + r1 + xm);
        const float b11 = __ldg(f1 + r1 + x);

        u = ((w00 * a00 + w10 * a10) + w01 * a01) + w11 * a11;
        v = ((w00 * b00 + w10 * b10) + w01 * b01) + w11 * b11;
    }

    // ---- t = 1..11: divergent scalar gathers, reference rounding order.
    #pragma unroll
    for (int t = 1; t < Tc; ++t) {
        const float* f0 = fb + (unsigned)t * (2 * HW);   // u plane
        const float* f1 = f0 + HW;                       // v plane

        // Reference order: (x + u) - 0.5 (do NOT hoist the -0.5).
        const float px = (xf + u) - 0.5f;
        const float py = (yf + v) - 0.5f;

        const int x0 = __float2int_rd(px);
        const int y0 = __float2int_rd(py);

        const float wx1 = px - (float)x0;
        const float wy1 = py - (float)y0;
        const float wx0 = 1.0f - wx1;
        const float wy0 = 1.0f - wy1;

        // Fold validity into axis weights (exact: x1.0 / x0.0).
        const float gx0 = ((x0 >= 0)  && (x0 <= Wc - 1)) ? wx0 : 0.0f;
        const float gx1 = ((x0 >= -1) && (x0 <= Wc - 2)) ? wx1 : 0.0f;
        const float gy0 = ((y0 >= 0)  && (y0 <= Hc - 1)) ? wy0 : 0.0f;
        const float gy1 = ((y0 >= -1) && (y0 <= Hc - 2)) ? wy1 : 0.0f;

        const float w00 = gx0 * gy0;
        const float w10 = gx1 * gy0;
        const float w01 = gx0 * gy1;
        const float w11 = gx1 * gy1;

        const int xc0 = min(max(x0, 0), Wc - 1);
        const int xc1 = min(max(x0 + 1, 0), Wc - 1);
        const int yc0 = min(max(y0, 0), Hc - 1);
        const int yc1 = min(max(y0 + 1, 0), Hc - 1);

        const int r0 = yc0 * Wc;
        const int r1 = yc1 * Wc;
        const int i00 = r0 + xc0;
        const int i10 = r0 + xc1;
        const int i01 = r1 + xc0;
        const int i11 = r1 + xc1;

        // 8 independent scalar gathers -> MLP 8.
        const float a00 = __ldg(f0 + i00);
        const float a10 = __ldg(f0 + i10);
        const float a01 = __ldg(f0 + i01);
        const float a11 = __ldg(f0 + i11);
        const float b00 = __ldg(f1 + i00);
        const float b10 = __ldg(f1 + i10);
        const float b01 = __ldg(f1 + i01);
        const float b11 = __ldg(f1 + i11);

        // Same summation order as reference: ((c00 + c10) + c01) + c11
        const float s0 = ((w00 * a00 + w10 * a10) + w01 * a01) + w11 * a11;
        const float s1 = ((w00 * b00 + w10 * b10) + w01 * b01) + w11 * b11;

        u += s0;
        v += s1;
    }

    const int p = y * Wc + x;
    float* ob = out + (unsigned)b * (2 * HW);
    ob[p]      = u;
    ob[HW + p] = v;
}

extern "C" void kernel_launch(void* const* d_in, const int* in_sizes, int n_in,
                              void* d_out, int out_size) {
    const float* flows = (const float*)d_in[0];
    float* out = (float*)d_out;

    dim3 grid(Wc / 32, Hc / 8, Bc);   // 30 x 68 x 8, exact cover
    dim3 block(256);
    flow_composite_kernel<<<grid, block>>>(flows, out);
}